// round 16
// baseline (speedup 1.0000x reference)
#include <cuda_runtime.h>
#include <cuda_bf16.h>
#include <cstdint>

// ---------------------------------------------------------------------------
// InfoNCE loss (gradcache): N=16384, D=128, t=0.07
// HMMA mma.sync bf16 + qq-symmetry + persistent 148-CTA balanced schedule.
// Global tile list over (rowblock k, tile s); each of 148 CTAs owns ~333
// tiles; rowsums flushed via atomicAdd at segment boundaries.
// ---------------------------------------------------------------------------

#define NROWS 16384
#define DIM   128
#define D4    32
#define BM    128
#define BN    64
#define KSTEPS 8
#define NSM    148
#define NTHREADS 512
#define NP1    258          // per row-block: 256 qd tiles + 2 straddle qq tiles
#define TOTAL  49280        // sum over k of T_k, T_k = 386 - 2*(k&1)
#define INV_T    14.285714285714286f
#define SCALE_L2 20.609929155556620f   // (1/0.07)*log2(e)

#define SMA_BYTES (BM*256)        // 32768
#define SMB_BYTES (BN*256)        // 16384
#define SMEM_TOTAL (SMA_BYTES + 3*SMB_BYTES)   // 81920

__device__ float g_qn[NROWS*DIM];
__device__ float g_dn[NROWS*DIM];
__device__ __nv_bfloat16 g_qb[NROWS*DIM];
__device__ __nv_bfloat16 g_db[NROWS*DIM];
__device__ float g_rowsum[NROWS];
__device__ float g_qqcol[NROWS];
__device__ float g_partial[64];
__device__ unsigned int g_ctr;

__device__ __forceinline__ uint32_t smem_u32(const void* p) {
    uint32_t a;
    asm("{ .reg .u64 t; cvta.to.shared.u64 t, %1; cvt.u32.u64 %0, t; }" : "=r"(a) : "l"(p));
    return a;
}

#define LDMATRIX_X4(r, addr) \
    asm volatile("ldmatrix.sync.aligned.m8n8.x4.shared.b16 {%0,%1,%2,%3}, [%4];" \
        : "=r"((r)[0]), "=r"((r)[1]), "=r"((r)[2]), "=r"((r)[3]) : "r"(addr))

#define MMA_16816(c, a, b0, b1) \
    asm volatile("mma.sync.aligned.m16n8k16.row.col.f32.bf16.bf16.f32 " \
        "{%0,%1,%2,%3}, {%4,%5,%6,%7}, {%8,%9}, {%0,%1,%2,%3};" \
        : "+f"((c)[0]), "+f"((c)[1]), "+f"((c)[2]), "+f"((c)[3]) \
        : "r"((a)[0]), "r"((a)[1]), "r"((a)[2]), "r"((a)[3]), "r"(b0), "r"(b1))

#define CP_ASYNC16(dst, src) \
    asm volatile("cp.async.cg.shared.global [%0], [%1], 16;" :: "r"(dst), "l"(src))
#define CP_COMMIT() asm volatile("cp.async.commit_group;" ::: "memory")
#define CP_WAIT(n)  asm volatile("cp.async.wait_group %0;" :: "n"(n) : "memory")

__device__ __forceinline__ uint32_t swz(int row, int u) {
    return (uint32_t)(row * 256 + ((u ^ (row & 7)) << 4));
}
__device__ __forceinline__ float ex2f(float x) {
    float e; asm("ex2.approx.f32 %0, %1;" : "=f"(e) : "f"(x)); return e;
}

// schedule helpers: T_k = 386-2*(k&1); P(k) = 385k + (k&1)
__device__ __forceinline__ int sched_P(int k) { return 385 * k + (k & 1); }
__device__ __forceinline__ int sched_T(int k) { return 386 - 2 * (k & 1); }
__device__ __forceinline__ int sched_k_of(int g) {
    int k = g / 385;
    if (k > 127) k = 127;
    if (sched_P(k) > g) k--;
    return k;
}

// partner j of block k for pair index i; n_low = k>>1
__device__ __forceinline__ int partner_j(int k, int n_low, int i) {
    return (i < n_low) ? (2 * i + (k & 1)) : (k + 1 + 2 * (i - n_low));
}
// source coltile (64-row q units) for qq tile t of block k
__device__ __forceinline__ int qq_coltile(int k, int n_low, int t) {
    if (t < 2) return 2 * k + t;               // straddle (own diagonal block)
    int i = (t - 2) >> 1, half = (t - 2) & 1;
    return 2 * partner_j(k, n_low, i) + half;  // partner
}

// ---------------------------------------------------------------------------
// Kernel 1: normalize rows; zero g_qqcol (blocks 0..63) and g_rowsum (64..127)
// ---------------------------------------------------------------------------
__global__ void k_normalize(const float* __restrict__ q, const float* __restrict__ d) {
    if (blockIdx.x < 64)        g_qqcol[blockIdx.x * 256 + threadIdx.x] = 0.f;
    else if (blockIdx.x < 128)  g_rowsum[(blockIdx.x - 64) * 256 + threadIdx.x] = 0.f;
    int warp = (blockIdx.x * (blockDim.x >> 5)) + (threadIdx.x >> 5);
    int lane = threadIdx.x & 31;
    const float* src; float* dstf; __nv_bfloat162* dstb; int row;
    if (warp < NROWS) { src = q; dstf = g_qn; dstb = reinterpret_cast<__nv_bfloat162*>(g_qb); row = warp; }
    else              { src = d; dstf = g_dn; dstb = reinterpret_cast<__nv_bfloat162*>(g_db); row = warp - NROWS; }
    const float4* s4 = reinterpret_cast<const float4*>(src) + row * D4;
    float4* d4 = reinterpret_cast<float4*>(dstf) + row * D4;
    float4 v = s4[lane];
    float ss = v.x*v.x + v.y*v.y + v.z*v.z + v.w*v.w;
    #pragma unroll
    for (int off = 16; off; off >>= 1) ss += __shfl_xor_sync(0xffffffffu, ss, off);
    float r = rsqrtf(ss);
    v.x *= r; v.y *= r; v.z *= r; v.w *= r;
    d4[lane] = v;
    dstb[row * 64 + lane * 2 + 0] = __float22bfloat162_rn(make_float2(v.x, v.y));
    dstb[row * 64 + lane * 2 + 1] = __float22bfloat162_rn(make_float2(v.z, v.w));
}

// ---------------------------------------------------------------------------
// prefetch tile s of block k into ring slot s%3, guarded by s < bound
__device__ __forceinline__ void prefetch_run(int s, int bound, int k, int n_low,
                                             uint32_t smB0, int tid) {
    if (s < bound) {
        const uint4* gs;
        if (s < 256) gs = reinterpret_cast<const uint4*>(g_db) + (size_t)s * BN * 16;
        else {
            int c = qq_coltile(k, n_low, s - 256);
            gs = reinterpret_cast<const uint4*>(g_qb) + (size_t)c * BN * 16;
        }
        uint32_t dstb = smB0 + (uint32_t)(s % 3) * SMB_BYTES;
        int row = tid >> 3, ub = (tid & 7) * 2;
        CP_ASYNC16(dstb + swz(row, ub + 0), gs + row * 16 + ub + 0);
        CP_ASYNC16(dstb + swz(row, ub + 1), gs + row * 16 + ub + 1);
    }
    CP_COMMIT();
}

// epilogue element e of accE: ex2, spread rowsum slot, optional colsum partial
template<int MODE>   // 1 = row only, 2 = row + col
__device__ __forceinline__ void epi_elem(int e, const float (&accE)[2][2][4],
                                         float (&rs8)[8], float (&cp)[4]) {
    int mf = e >> 3, n8 = (e >> 2) & 1, r = e & 3;
    float ex = ex2f(accE[mf][n8][r] * SCALE_L2);
    rs8[(mf * 2 + (r >> 1)) * 2 + (e & 1)] += ex;
    if (MODE == 2) cp[n8 * 2 + (r & 1)] += ex;
}

// MMA one tile into acc; interleaved epilogue of accE per MODE (0 = none)
template<int MODE>
__device__ __forceinline__ void mma_tile(
    uint32_t smB, int lane, int nw,
    const uint32_t (&afr)[KSTEPS][2][4],
    float (&acc)[2][2][4], float (&accE)[2][2][4],
    float (&rs8)[8], float (&cp)[4])
{
    #pragma unroll
    for (int mf = 0; mf < 2; mf++)
        #pragma unroll
        for (int n8 = 0; n8 < 2; n8++)
            #pragma unroll
            for (int r = 0; r < 4; r++) acc[mf][n8][r] = 0.f;

    #pragma unroll
    for (int ks = 0; ks < KSTEPS; ks++) {
        uint32_t bfr[4];
        {
            int row = nw + (lane & 7) + ((lane >> 4) << 3);
            int unit = 2 * ks + ((lane >> 3) & 1);
            LDMATRIX_X4(bfr, smB + swz(row, unit));
        }
        #pragma unroll
        for (int mf = 0; mf < 2; mf++)
            #pragma unroll
            for (int n8 = 0; n8 < 2; n8++)
                MMA_16816(acc[mf][n8], afr[ks][mf], bfr[n8 * 2], bfr[n8 * 2 + 1]);
        if (MODE >= 1) {
            epi_elem<MODE>(ks * 2 + 0, accE, rs8, cp);
            epi_elem<MODE>(ks * 2 + 1, accE, rs8, cp);
        }
    }
}

// reduce column partials across row-lanes, atomically scatter to g_qqcol
__device__ __forceinline__ void scatter_cols(float (&cp)[4], int c, int lane, int nw) {
    #pragma unroll
    for (int j4 = 0; j4 < 4; j4++) {
        cp[j4] += __shfl_down_sync(0xffffffffu, cp[j4], 4);
        cp[j4] += __shfl_down_sync(0xffffffffu, cp[j4], 8);
        cp[j4] += __shfl_down_sync(0xffffffffu, cp[j4], 16);
    }
    if (lane < 4) {
        const int base = c * 64 + nw;
        #pragma unroll
        for (int j4 = 0; j4 < 4; j4++)
            atomicAdd(&g_qqcol[base + (j4 >> 1) * 8 + lane * 2 + (j4 & 1)], cp[j4]);
    }
}

// run the pipeline over tiles [a, b) of block k (same MODE throughout).
template<int MODE>
__device__ __forceinline__ void run_tiles(
    int a, int b, int k, int n_low, int tid, int lane, int nw, uint32_t smB0,
    const uint32_t (&afr)[KSTEPS][2][4], float (&rs8)[8])
{
    if (a >= b) return;
    float acc0[2][2][4], acc1[2][2][4], cp[4] = {0.f, 0.f, 0.f, 0.f};

    CP_WAIT(0);
    __syncthreads();             // prior run's readers done before slot reuse
    prefetch_run(a,     b, k, n_low, smB0, tid);
    prefetch_run(a + 1, b, k, n_low, smB0, tid);

    bool flip = false;           // which acc the NEXT tile writes (false->acc0)
    for (int s = a; s < b; s++) {
        CP_WAIT(1);
        __syncthreads();
        prefetch_run(s + 2, b, k, n_low, smB0, tid);
        uint32_t smB = smB0 + (uint32_t)(s % 3) * SMB_BYTES;
        if (s == a) {
            mma_tile<0>(smB, lane, nw, afr, acc0, acc1, rs8, cp);
        } else {
            if (MODE == 2) { cp[0] = cp[1] = cp[2] = cp[3] = 0.f; }
            if (flip) mma_tile<MODE>(smB, lane, nw, afr, acc1, acc0, rs8, cp);
            else      mma_tile<MODE>(smB, lane, nw, afr, acc0, acc1, rs8, cp);
            if (MODE == 2) scatter_cols(cp, qq_coltile(k, n_low, (s - 1) - 256), lane, nw);
        }
        flip = !flip;
    }
    // drain last tile: it lives in acc0 if flip==true else acc1
    if (MODE == 2) { cp[0] = cp[1] = cp[2] = cp[3] = 0.f; }
    if (flip) {
        #pragma unroll
        for (int e = 0; e < 16; e++) epi_elem<MODE>(e, acc0, rs8, cp);
    } else {
        #pragma unroll
        for (int e = 0; e < 16; e++) epi_elem<MODE>(e, acc1, rs8, cp);
    }
    if (MODE == 2) scatter_cols(cp, qq_coltile(k, n_low, (b - 1) - 256), lane, nw);
}

// ---------------------------------------------------------------------------
// 148 persistent CTAs x 512 threads (16 warps: 4M x 4N, warp tile 32x16)
// ---------------------------------------------------------------------------
__global__ void __launch_bounds__(NTHREADS, 1) k_main() {
    extern __shared__ char smem[];
    const int tid = threadIdx.x;
    const int w = tid >> 5, lane = tid & 31;
    const uint32_t smA = smem_u32(smem);
    const uint32_t smB0 = smA + SMA_BYTES;

    const int mw = (w >> 2) * 32;   // 4 M-warps
    const int nw = (w & 3) * 16;    // 4 N-warps

    // this CTA's slice of the global tile list
    long long c = (long long)blockIdx.x;
    int g  = (int)((c * TOTAL) / NSM);
    int g1 = (int)(((c + 1) * TOTAL) / NSM);

    while (g < g1) {
        const int k = sched_k_of(g);
        const int n_low = k >> 1;
        const int Tk = sched_T(k);
        const int s0 = g - sched_P(k);
        const int s1 = (s0 + (g1 - g) < Tk) ? (s0 + (g1 - g)) : Tk;

        // stage A tile for block k (syncthreads in run_tiles orders this
        // against prior segment's sred readers and B-slot readers)
        __syncthreads();
        {
            const uint4* ga = reinterpret_cast<const uint4*>(g_qb) + (size_t)k * BM * 16;
            int row = tid >> 2, ub = (tid & 3) * 4;
            #pragma unroll
            for (int j = 0; j < 4; j++)
                *reinterpret_cast<uint4*>(smem + swz(row, ub + j)) = ga[row * 16 + ub + j];
        }
        __syncthreads();

        // A fragments register-resident for this segment
        uint32_t afr[KSTEPS][2][4];
        #pragma unroll
        for (int ks = 0; ks < KSTEPS; ks++)
            #pragma unroll
            for (int mf = 0; mf < 2; mf++) {
                int row = mw + mf * 16 + (lane & 15);
                int unit = 2 * ks + (lane >> 4);
                LDMATRIX_X4(afr[ks][mf], smA + swz(row, unit));
            }

        float rs8[8] = {0.f,0.f,0.f,0.f,0.f,0.f,0.f,0.f};

        // phase runs: MODE 1 for s<NP1 (qd + straddle), MODE 2 for partners
        int m1_end = (s1 < NP1) ? s1 : NP1;
        run_tiles<1>(s0, m1_end, k, n_low, tid, lane, nw, smB0, afr, rs8);
        int m2_beg = (s0 > NP1) ? s0 : NP1;
        run_tiles<2>(m2_beg, s1, k, n_low, tid, lane, nw, smB0, afr, rs8);

        // flush rowsums for block k (atomic: blocks shared across CTAs)
        CP_WAIT(0);
        __syncthreads();
        float rsv[4];
        #pragma unroll
        for (int gg = 0; gg < 4; gg++) rsv[gg] = rs8[2 * gg] + rs8[2 * gg + 1];
        float* sred = reinterpret_cast<float*>(smem);   // reuse A region
        #pragma unroll
        for (int j = 0; j < 4; j++) {
            float s = rsv[j];
            s += __shfl_xor_sync(0xffffffffu, s, 1);
            s += __shfl_xor_sync(0xffffffffu, s, 2);
            if ((lane & 3) == 0) {
                int rl = mw + (j >> 1) * 16 + (j & 1) * 8 + (lane >> 2);
                sred[rl * 4 + (w & 3)] = s;
            }
        }
        __syncthreads();
        if (tid < 128)
            atomicAdd(&g_rowsum[k * BM + tid],
                      sred[tid * 4] + sred[tid * 4 + 1] + sred[tid * 4 + 2] + sred[tid * 4 + 3]);

        g += s1 - s0;
    }
}

// ---------------------------------------------------------------------------
// Kernel 3: per-row finalize (row+col sums, self-term, log, dot) + reduce
// ---------------------------------------------------------------------------
__global__ void k_finalize(float* __restrict__ out) {
    const int tid = threadIdx.x;
    const int row = blockIdx.x * 256 + tid;

    float sv = g_rowsum[row] + g_qqcol[row];
    const __nv_bfloat162* qb2 = reinterpret_cast<const __nv_bfloat162*>(g_qb) + (size_t)row * 64;
    float ps = 0.f;
    #pragma unroll
    for (int i = 0; i < 64; i++) {
        float2 f = __bfloat1622float2(qb2[i]);
        ps += f.x * f.x + f.y * f.y;
    }
    sv -= ex2f(ps * SCALE_L2);
    const float4* q4 = reinterpret_cast<const float4*>(g_qn) + (size_t)row * D4;
    const float4* d4 = reinterpret_cast<const float4*>(g_dn) + (size_t)row * D4;
    float p = 0.f;
    #pragma unroll
    for (int i = 0; i < D4; i++) {
        float4 a = q4[i], b = d4[i];
        p += a.x*b.x + a.y*b.y + a.z*b.z + a.w*b.w;
    }
    float term = logf(sv) - p * INV_T;

    #pragma unroll
    for (int off = 16; off; off >>= 1) term += __shfl_xor_sync(0xffffffffu, term, off);
    __shared__ float ws[8];
    if ((tid & 31) == 0) ws[tid >> 5] = term;
    __syncthreads();

    __shared__ unsigned int s_rank;
    if (tid == 0) {
        float s = 0.f;
        #pragma unroll
        for (int i = 0; i < 8; i++) s += ws[i];
        g_partial[blockIdx.x] = s;
        __threadfence();
        s_rank = atomicAdd(&g_ctr, 1u);
    }
    __syncthreads();
    if (tid == 0 && s_rank == 63) {
        float s = 0.f;
        for (int i = 0; i < 64; i++) s += __ldcg(&g_partial[i]);
        out[0] = s * (1.0f / NROWS);
        g_ctr = 0;                      // reset for next graph replay
        __threadfence();
    }
}

extern "C" void kernel_launch(void* const* d_in, const int* in_sizes, int n_in,
                              void* d_out, int out_size) {
    const float* q = (const float*)d_in[0];
    const float* d = (const float*)d_in[1];
    float* out = (float*)d_out;

    cudaFuncSetAttribute(k_main, cudaFuncAttributeMaxDynamicSharedMemorySize, SMEM_TOTAL);

    k_normalize<<<(2 * NROWS) / 8, 256>>>(q, d);
    k_main<<<NSM, NTHREADS, SMEM_TOTAL>>>();
    k_finalize<<<64, 256>>>(out);
}

// round 17
// speedup vs baseline: 1.3406x; 1.3406x over previous
#include <cuda_runtime.h>
#include <cuda_bf16.h>
#include <cstdint>

// ---------------------------------------------------------------------------
// InfoNCE loss (gradcache): N=16384, D=128, t=0.07
// HMMA mma.sync bf16 + qq-symmetry (R15 structure). R17: init-form MMA for
// ks=0 (no accumulator zeroing) + hoisted B-address math.
// ---------------------------------------------------------------------------

#define NROWS 16384
#define DIM   128
#define D4    32
#define BM    128
#define BN    64
#define KSTEPS 8
#define NCTAS  128
#define NTHREADS 512
#define NP1    258          // phase 1: 256 qd tiles + 2 straddle qq tiles
#define INV_T    14.285714285714286f
#define SCALE_L2 20.609929155556620f   // (1/0.07)*log2(e)

#define SMA_BYTES (BM*256)        // 32768
#define SMB_BYTES (BN*256)        // 16384
#define SMEM_TOTAL (SMA_BYTES + 3*SMB_BYTES)   // 81920

__device__ float g_qn[NROWS*DIM];
__device__ float g_dn[NROWS*DIM];
__device__ __nv_bfloat16 g_qb[NROWS*DIM];
__device__ __nv_bfloat16 g_db[NROWS*DIM];
__device__ float g_rowsum[NROWS];
__device__ float g_qqcol[NROWS];
__device__ float g_partial[64];
__device__ unsigned int g_ctr;

__device__ __forceinline__ uint32_t smem_u32(const void* p) {
    uint32_t a;
    asm("{ .reg .u64 t; cvta.to.shared.u64 t, %1; cvt.u32.u64 %0, t; }" : "=r"(a) : "l"(p));
    return a;
}

#define LDMATRIX_X4(r, addr) \
    asm volatile("ldmatrix.sync.aligned.m8n8.x4.shared.b16 {%0,%1,%2,%3}, [%4];" \
        : "=r"((r)[0]), "=r"((r)[1]), "=r"((r)[2]), "=r"((r)[3]) : "r"(addr))

#define MMA_16816(c, a, b0, b1) \
    asm volatile("mma.sync.aligned.m16n8k16.row.col.f32.bf16.bf16.f32 " \
        "{%0,%1,%2,%3}, {%4,%5,%6,%7}, {%8,%9}, {%0,%1,%2,%3};" \
        : "+f"((c)[0]), "+f"((c)[1]), "+f"((c)[2]), "+f"((c)[3]) \
        : "r"((a)[0]), "r"((a)[1]), "r"((a)[2]), "r"((a)[3]), "r"(b0), "r"(b1))

// init form: D = A*B + {z,z,z,z} (no prior accumulator read, no zero MOVs)
#define MMA_16816_INIT(c, a, b0, b1, z) \
    asm volatile("mma.sync.aligned.m16n8k16.row.col.f32.bf16.bf16.f32 " \
        "{%0,%1,%2,%3}, {%4,%5,%6,%7}, {%8,%9}, {%10,%10,%10,%10};" \
        : "=f"((c)[0]), "=f"((c)[1]), "=f"((c)[2]), "=f"((c)[3]) \
        : "r"((a)[0]), "r"((a)[1]), "r"((a)[2]), "r"((a)[3]), "r"(b0), "r"(b1), "f"(z))

#define CP_ASYNC16(dst, src) \
    asm volatile("cp.async.cg.shared.global [%0], [%1], 16;" :: "r"(dst), "l"(src))
#define CP_COMMIT() asm volatile("cp.async.commit_group;" ::: "memory")
#define CP_WAIT(n)  asm volatile("cp.async.wait_group %0;" :: "n"(n) : "memory")

__device__ __forceinline__ uint32_t swz(int row, int u) {
    return (uint32_t)(row * 256 + ((u ^ (row & 7)) << 4));
}
__device__ __forceinline__ float ex2f(float x) {
    float e; asm("ex2.approx.f32 %0, %1;" : "=f"(e) : "f"(x)); return e;
}

// partner j of CTA k for pair index i (0..n_part-1), n_low = k>>1
__device__ __forceinline__ int partner_j(int k, int n_low, int i) {
    return (i < n_low) ? (2 * i + (k & 1)) : (k + 1 + 2 * (i - n_low));
}
// source coltile index (64-row q units) for qq tile t (t>=0)
__device__ __forceinline__ int qq_coltile(int k, int n_low, int t) {
    if (t < 2) return 2 * k + t;               // straddle (own diagonal block)
    int i = (t - 2) >> 1, half = (t - 2) & 1;
    return 2 * partner_j(k, n_low, i) + half;  // partner
}

// ---------------------------------------------------------------------------
// Kernel 1: L2-normalize rows; also zero g_qqcol (blocks 0..63)
// ---------------------------------------------------------------------------
__global__ void k_normalize(const float* __restrict__ q, const float* __restrict__ d) {
    if (blockIdx.x < 64) g_qqcol[blockIdx.x * 256 + threadIdx.x] = 0.f;
    int warp = (blockIdx.x * (blockDim.x >> 5)) + (threadIdx.x >> 5);
    int lane = threadIdx.x & 31;
    const float* src; float* dstf; __nv_bfloat162* dstb; int row;
    if (warp < NROWS) { src = q; dstf = g_qn; dstb = reinterpret_cast<__nv_bfloat162*>(g_qb); row = warp; }
    else              { src = d; dstf = g_dn; dstb = reinterpret_cast<__nv_bfloat162*>(g_db); row = warp - NROWS; }
    const float4* s4 = reinterpret_cast<const float4*>(src) + row * D4;
    float4* d4 = reinterpret_cast<float4*>(dstf) + row * D4;
    float4 v = s4[lane];
    float ss = v.x*v.x + v.y*v.y + v.z*v.z + v.w*v.w;
    #pragma unroll
    for (int off = 16; off; off >>= 1) ss += __shfl_xor_sync(0xffffffffu, ss, off);
    float r = rsqrtf(ss);
    v.x *= r; v.y *= r; v.z *= r; v.w *= r;
    d4[lane] = v;
    dstb[row * 64 + lane * 2 + 0] = __float22bfloat162_rn(make_float2(v.x, v.y));
    dstb[row * 64 + lane * 2 + 1] = __float22bfloat162_rn(make_float2(v.z, v.w));
}

// ---------------------------------------------------------------------------
// prefetch tile for step s into ring buffer s % 3 (2 x 16B per thread)
__device__ __forceinline__ void prefetch_step(int s, int nt_total, int k, int n_low,
                                              uint32_t smB0, int tid) {
    if (s < nt_total) {
        const uint4* gs;
        if (s < 256) gs = reinterpret_cast<const uint4*>(g_db) + (size_t)s * BN * 16;
        else {
            int c = qq_coltile(k, n_low, s - 256);
            gs = reinterpret_cast<const uint4*>(g_qb) + (size_t)c * BN * 16;
        }
        uint32_t dstb = smB0 + (uint32_t)(s % 3) * SMB_BYTES;
        int row = tid >> 3, ub = (tid & 7) * 2;
        CP_ASYNC16(dstb + swz(row, ub + 0), gs + row * 16 + ub + 0);
        CP_ASYNC16(dstb + swz(row, ub + 1), gs + row * 16 + ub + 1);
    }
    CP_COMMIT();
}

// epilogue element e of accE: ex2, spread-slot rowsum add, optional colsum add
template<int MODE>   // 1 = row only, 2 = row + col
__device__ __forceinline__ void epi_elem(int e, const float (&accE)[2][2][4],
                                         float (&rs8)[8], float (&cp)[4]) {
    int mf = e >> 3, n8 = (e >> 2) & 1, r = e & 3;
    float ex = ex2f(accE[mf][n8][r] * SCALE_L2);
    rs8[(mf * 2 + (r >> 1)) * 2 + (e & 1)] += ex;
    if (MODE == 2) cp[n8 * 2 + (r & 1)] += ex;
}

// MMA one tile into acc; interleaved epilogue of accE per MODE (0 = none)
template<int MODE>
__device__ __forceinline__ void mma_tile(
    uint32_t smB, int lane, int nw,
    const uint32_t (&afr)[KSTEPS][2][4],
    float (&acc)[2][2][4], float (&accE)[2][2][4],
    float (&rs8)[8], float (&cp)[4])
{
    // hoisted B-address math
    const int brow = nw + (lane & 7) + ((lane >> 4) << 3);
    const int bsel = (lane >> 3) & 1;
    const uint32_t bbase = smB + (uint32_t)(brow * 256);
    const int bx7 = brow & 7;

    #pragma unroll
    for (int ks = 0; ks < KSTEPS; ks++) {
        uint32_t bfr[4];
        LDMATRIX_X4(bfr, bbase + (uint32_t)((((2 * ks + bsel) ^ bx7)) << 4));
        if (ks == 0) {
            #pragma unroll
            for (int mf = 0; mf < 2; mf++)
                #pragma unroll
                for (int n8 = 0; n8 < 2; n8++)
                    MMA_16816_INIT(acc[mf][n8], afr[ks][mf], bfr[n8 * 2], bfr[n8 * 2 + 1], 0.f);
        } else {
            #pragma unroll
            for (int mf = 0; mf < 2; mf++)
                #pragma unroll
                for (int n8 = 0; n8 < 2; n8++)
                    MMA_16816(acc[mf][n8], afr[ks][mf], bfr[n8 * 2], bfr[n8 * 2 + 1]);
        }
        if (MODE >= 1) {
            epi_elem<MODE>(ks * 2 + 0, accE, rs8, cp);
            epi_elem<MODE>(ks * 2 + 1, accE, rs8, cp);
        }
    }
}

// reduce column partials across row-lanes and atomically scatter to g_qqcol
__device__ __forceinline__ void scatter_cols(float (&cp)[4], int c, int lane, int nw) {
    #pragma unroll
    for (int j4 = 0; j4 < 4; j4++) {
        cp[j4] += __shfl_down_sync(0xffffffffu, cp[j4], 4);
        cp[j4] += __shfl_down_sync(0xffffffffu, cp[j4], 8);
        cp[j4] += __shfl_down_sync(0xffffffffu, cp[j4], 16);
    }
    if (lane < 4) {
        const int base = c * 64 + nw;
        #pragma unroll
        for (int j4 = 0; j4 < 4; j4++)
            atomicAdd(&g_qqcol[base + (j4 >> 1) * 8 + lane * 2 + (j4 & 1)], cp[j4]);
    }
}

template<int MODE>
__device__ __forceinline__ void tile_step(
    int s, int nt_total, int k, int n_low, int tid, int lane, int nw, uint32_t smB0,
    const uint32_t (&afr)[KSTEPS][2][4],
    float (&acc)[2][2][4], float (&accE)[2][2][4], float (&rs8)[8], float (&cp)[4])
{
    CP_WAIT(1);
    __syncthreads();
    prefetch_step(s + 2, nt_total, k, n_low, smB0, tid);
    mma_tile<MODE>(smB0 + (uint32_t)(s % 3) * SMB_BYTES, lane, nw, afr, acc, accE, rs8, cp);
}

// ---------------------------------------------------------------------------
// 128 CTAs x 512 threads (16 warps: 4M x 4N, warp tile 32x16)
// ---------------------------------------------------------------------------
__global__ void __launch_bounds__(NTHREADS, 1) k_main() {
    extern __shared__ char smem[];
    const int tid = threadIdx.x;
    const int w = tid >> 5, lane = tid & 31;
    const int k = (int)blockIdx.x;
    const int n_low = k >> 1;
    const int n_part = 64 - (k & 1);
    const int nt_total = NP1 + 2 * n_part;  // 386 (even k) / 384 (odd k)
    const uint32_t smA = smem_u32(smem);
    const uint32_t smB0 = smA + SMA_BYTES;

    const int mw = (w >> 2) * 32;   // 4 M-warps
    const int nw = (w & 3) * 16;    // 4 N-warps

    // stage A tile (this CTA's 128 q-rows)
    {
        const uint4* ga = reinterpret_cast<const uint4*>(g_qb) + (size_t)k * BM * 16;
        int row = tid >> 2, ub = (tid & 3) * 4;
        #pragma unroll
        for (int j = 0; j < 4; j++)
            *reinterpret_cast<uint4*>(smem + swz(row, ub + j)) = ga[row * 16 + ub + j];
    }
    prefetch_step(0, nt_total, k, n_low, smB0, tid);
    prefetch_step(1, nt_total, k, n_low, smB0, tid);
    __syncthreads();

    // A fragments register-resident (64 regs)
    uint32_t afr[KSTEPS][2][4];
    #pragma unroll
    for (int ks = 0; ks < KSTEPS; ks++)
        #pragma unroll
        for (int mf = 0; mf < 2; mf++) {
            int row = mw + mf * 16 + (lane & 15);
            int unit = 2 * ks + (lane >> 4);
            LDMATRIX_X4(afr[ks][mf], smA + swz(row, unit));
        }

    float acc0[2][2][4], acc1[2][2][4];
    float rs8[8] = {0.f,0.f,0.f,0.f,0.f,0.f,0.f,0.f};
    float cp[4] = {0.f,0.f,0.f,0.f};

    // ---- phase 1: 258 tiles (qd + 2 straddle), interleaved row epilogue ----
    tile_step<0>(0, nt_total, k, n_low, tid, lane, nw, smB0, afr, acc0, acc1, rs8, cp);
    for (int s = 1; s + 1 < NP1; s += 2) {
        tile_step<1>(s,     nt_total, k, n_low, tid, lane, nw, smB0, afr, acc1, acc0, rs8, cp);
        tile_step<1>(s + 1, nt_total, k, n_low, tid, lane, nw, smB0, afr, acc0, acc1, rs8, cp);
    }
    tile_step<1>(NP1 - 1, nt_total, k, n_low, tid, lane, nw, smB0, afr, acc1, acc0, rs8, cp);
    // drain epilogue of tile NP1-1 (in acc1)
    #pragma unroll
    for (int e = 0; e < 16; e++) epi_elem<1>(e, acc1, rs8, cp);

    // ---- phase 2: 2*n_part partner tiles (even count), pipelined epilogue ----
    tile_step<0>(NP1, nt_total, k, n_low, tid, lane, nw, smB0, afr, acc0, acc1, rs8, cp);
    for (int s = NP1 + 1; s + 1 < nt_total; s += 2) {
        #pragma unroll
        for (int j4 = 0; j4 < 4; j4++) cp[j4] = 0.f;
        tile_step<2>(s, nt_total, k, n_low, tid, lane, nw, smB0, afr, acc1, acc0, rs8, cp);
        scatter_cols(cp, qq_coltile(k, n_low, s - 1 - 256), lane, nw);
        #pragma unroll
        for (int j4 = 0; j4 < 4; j4++) cp[j4] = 0.f;
        tile_step<2>(s + 1, nt_total, k, n_low, tid, lane, nw, smB0, afr, acc0, acc1, rs8, cp);
        scatter_cols(cp, qq_coltile(k, n_low, s - 256), lane, nw);
    }
    // remaining: tile nt_total-1 (MMA into acc1, epilogue acc0 = tile nt_total-2)
    #pragma unroll
    for (int j4 = 0; j4 < 4; j4++) cp[j4] = 0.f;
    tile_step<2>(nt_total - 1, nt_total, k, n_low, tid, lane, nw, smB0, afr, acc1, acc0, rs8, cp);
    scatter_cols(cp, qq_coltile(k, n_low, nt_total - 2 - 256), lane, nw);
    // drain last tile (acc1)
    #pragma unroll
    for (int j4 = 0; j4 < 4; j4++) cp[j4] = 0.f;
    #pragma unroll
    for (int e = 0; e < 16; e++) epi_elem<2>(e, acc1, rs8, cp);
    scatter_cols(cp, qq_coltile(k, n_low, nt_total - 1 - 256), lane, nw);

    __syncthreads();   // smem free for reductions

    // collapse spread slots, combine 4 N-warps per row; write row sums
    float rs[4];
    #pragma unroll
    for (int g = 0; g < 4; g++) rs[g] = rs8[2 * g] + rs8[2 * g + 1];

    float* sred = reinterpret_cast<float*>(smem);   // [128][4]
    #pragma unroll
    for (int j = 0; j < 4; j++) {
        float s = rs[j];
        s += __shfl_xor_sync(0xffffffffu, s, 1);
        s += __shfl_xor_sync(0xffffffffu, s, 2);
        if ((lane & 3) == 0) {
            int rl = mw + (j >> 1) * 16 + (j & 1) * 8 + (lane >> 2);
            sred[rl * 4 + (w & 3)] = s;
        }
    }
    __syncthreads();
    if (tid < 128)
        g_rowsum[k * BM + tid] =
            sred[tid * 4] + sred[tid * 4 + 1] + sred[tid * 4 + 2] + sred[tid * 4 + 3];
}

// ---------------------------------------------------------------------------
// Kernel 3: per-row finalize (row+col sums, self-term, log, dot) + reduce
// ---------------------------------------------------------------------------
__global__ void k_finalize(float* __restrict__ out) {
    const int tid = threadIdx.x;
    const int row = blockIdx.x * 256 + tid;

    float sv = g_rowsum[row] + g_qqcol[row];
    const __nv_bfloat162* qb2 = reinterpret_cast<const __nv_bfloat162*>(g_qb) + (size_t)row * 64;
    float ps = 0.f;
    #pragma unroll
    for (int i = 0; i < 64; i++) {
        float2 f = __bfloat1622float2(qb2[i]);
        ps += f.x * f.x + f.y * f.y;
    }
    sv -= ex2f(ps * SCALE_L2);
    const float4* q4 = reinterpret_cast<const float4*>(g_qn) + (size_t)row * D4;
    const float4* d4 = reinterpret_cast<const float4*>(g_dn) + (size_t)row * D4;
    float p = 0.f;
    #pragma unroll
    for (int i = 0; i < D4; i++) {
        float4 a = q4[i], b = d4[i];
        p += a.x*b.x + a.y*b.y + a.z*b.z + a.w*b.w;
    }
    float term = logf(sv) - p * INV_T;

    #pragma unroll
    for (int off = 16; off; off >>= 1) term += __shfl_xor_sync(0xffffffffu, term, off);
    __shared__ float ws[8];
    if ((tid & 31) == 0) ws[tid >> 5] = term;
    __syncthreads();

    __shared__ unsigned int s_rank;
    if (tid == 0) {
        float s = 0.f;
        #pragma unroll
        for (int i = 0; i < 8; i++) s += ws[i];
        g_partial[blockIdx.x] = s;
        __threadfence();
        s_rank = atomicAdd(&g_ctr, 1u);
    }
    __syncthreads();
    if (tid == 0 && s_rank == 63) {
        float s = 0.f;
        for (int i = 0; i < 64; i++) s += __ldcg(&g_partial[i]);
        out[0] = s * (1.0f / NROWS);
        g_ctr = 0;                      // reset for next graph replay
        __threadfence();
    }
}

extern "C" void kernel_launch(void* const* d_in, const int* in_sizes, int n_in,
                              void* d_out, int out_size) {
    const float* q = (const float*)d_in[0];
    const float* d = (const float*)d_in[1];
    float* out = (float*)d_out;

    cudaFuncSetAttribute(k_main, cudaFuncAttributeMaxDynamicSharedMemorySize, SMEM_TOTAL);

    k_normalize<<<(2 * NROWS) / 8, 256>>>(q, d);
    k_main<<<NCTAS, NTHREADS, SMEM_TOTAL>>>();
    k_finalize<<<64, 256>>>(out);
}